// round 1
// baseline (speedup 1.0000x reference)
#include <cuda_runtime.h>

// Problem shape (fixed per dataset): input1/2 [4,3,720,1280] f32, flow3/4 [4,2,720,1280] f32
namespace {
constexpr int Wd  = 1280;
constexpr int Hd  = 720;
constexpr int Bd  = 4;
constexpr int HW  = Hd * Wd;
constexpr int BHW = Bd * HW;

constexpr float INV_LE  = 255.0f / 30.0f;            // 1 / LAMBDA_E
constexpr float INV2S2  = 1.0f / (2.0f * 1.5f * 1.5f); // 1/(2*sigma_d^2)
constexpr float THRESH_ = 1e-6f;
constexpr float EPS_    = 1e-6f;
}

// Scratch: branch-indexed. acc4 = (p_r, p_g, p_b, pw), accR = rw.
__device__ float  g_err[2][BHW];
__device__ float  g_fw [2][BHW];
__device__ float4 g_acc4[2][BHW];
__device__ float  g_accR[2][BHW];

// ---------------------------------------------------------------------------
// Zero the splat accumulators (graph-capturable, no memset-on-symbol needed)
// ---------------------------------------------------------------------------
__global__ void __launch_bounds__(256) k_zero() {
    int p = blockIdx.x * 256 + threadIdx.x;
    if (p < 2 * BHW) {
        (&g_acc4[0][0])[p] = make_float4(0.f, 0.f, 0.f, 0.f);
        (&g_accR[0][0])[p] = 0.f;
    }
}

// ---------------------------------------------------------------------------
// Photometric error: err = mean_c | i1 - bilinear_warp(i2, flow) |
// ---------------------------------------------------------------------------
__global__ void __launch_bounds__(256) k_err(
    const float* __restrict__ i1, const float* __restrict__ i2,
    const float* __restrict__ flow, int br)
{
    int p = blockIdx.x * 256 + threadIdx.x;
    if (p >= BHW) return;
    int x  = p % Wd;
    int yb = p / Wd;           // b*H + y
    int b  = yb / Hd;
    int y  = yb - b * Hd;
    int r  = p - b * HW;       // y*W + x

    float u = flow[b * 2 * HW + r];
    float v = flow[b * 2 * HW + HW + r];

    float gx = fminf(fmaxf((float)x + u, 0.f), (float)(Wd - 1));
    float gy = fminf(fmaxf((float)y + v, 0.f), (float)(Hd - 1));
    float x0f = floorf(gx), y0f = floorf(gy);
    int x0 = (int)x0f, y0 = (int)y0f;
    int x1 = min(x0 + 1, Wd - 1), y1 = min(y0 + 1, Hd - 1);
    float wx = gx - x0f, wy = gy - y0f;
    float w00 = (1.f - wx) * (1.f - wy);
    float w01 = wx * (1.f - wy);
    float w10 = (1.f - wx) * wy;
    float w11 = wx * wy;

    const float* i2b = i2 + b * 3 * HW;
    const float* i1b = i1 + b * 3 * HW;
    float e = 0.f;
#pragma unroll
    for (int c = 0; c < 3; c++) {
        const float* ip = i2b + c * HW;
        float wv = __ldg(ip + y0 * Wd + x0) * w00 + __ldg(ip + y0 * Wd + x1) * w01
                 + __ldg(ip + y1 * Wd + x0) * w10 + __ldg(ip + y1 * Wd + x1) * w11;
        e += fabsf(__ldg(i1b + c * HW + r) - wv);
    }
    g_err[br][p] = e * (1.f / 3.f);
}

// ---------------------------------------------------------------------------
// 3x3 box filter (zero-padded SAME, /9 always) + fw = exp(-(err/lambda_e)^2)
// ---------------------------------------------------------------------------
__global__ void __launch_bounds__(256) k_fw(int br) {
    int p = blockIdx.x * 256 + threadIdx.x;
    if (p >= BHW) return;
    int x  = p % Wd;
    int yb = p / Wd;
    int b  = yb / Hd;
    int y  = yb - b * Hd;

    const float* eb = g_err[br] + b * HW;
    float s = 0.f;
#pragma unroll
    for (int dy = -1; dy <= 1; dy++) {
        int yy = y + dy;
        if ((unsigned)yy >= (unsigned)Hd) continue;
#pragma unroll
        for (int dx = -1; dx <= 1; dx++) {
            int xx = x + dx;
            if ((unsigned)xx >= (unsigned)Wd) continue;
            s += eb[yy * Wd + xx];
        }
    }
    float t = s * (1.f / 9.f) * INV_LE;
    g_fw[br][p] = expf(-t * t);   // LAMBDA_V = 1
}

// ---------------------------------------------------------------------------
// Forward gaussian splat: each pixel scatters 16 taps.
// Per tap: one red.v4 (colors*fw, fw) + one scalar red (rw).
// TAO_R truncation is provably never active for PROW=2, sigma=1.5 (max d^2 = 8,
// exp(-8/4.5)=0.169 > 0.05) so it is dropped — result identical to reference.
// ---------------------------------------------------------------------------
__global__ void __launch_bounds__(256) k_splat(
    const float* __restrict__ img, const float* __restrict__ flow, int br)
{
    int p = blockIdx.x * 256 + threadIdx.x;
    if (p >= BHW) return;
    int x  = p % Wd;
    int yb = p / Wd;
    int b  = yb / Hd;
    int y  = yb - b * Hd;
    int r  = p - b * HW;

    float u = flow[b * 2 * HW + r];
    float v = flow[b * 2 * HW + HW + r];
    float f = g_fw[br][p];

    const float* imb = img + b * 3 * HW + r;
    float s0 = __ldg(imb) * f;
    float s1 = __ldg(imb + HW) * f;
    float s2 = __ldg(imb + 2 * HW) * f;

    float tx = (float)x + u, ty = (float)y + v;
    float fx = floorf(tx), fy = floorf(ty);
    int ix0 = (int)fx - 1, iy0 = (int)fy - 1;

    float gxv[4], gyv[4];
#pragma unroll
    for (int k = 0; k < 4; k++) {
        float dx = tx - (fx + (float)(k - 1));
        float dy = ty - (fy + (float)(k - 1));
        gxv[k] = expf(-dx * dx * INV2S2);
        gyv[k] = expf(-dy * dy * INV2S2);
    }

    float4* acc  = g_acc4[br];
    float*  accR = g_accR[br];
#pragma unroll
    for (int j = 0; j < 4; j++) {
        int iy = iy0 + j;
        if ((unsigned)iy >= (unsigned)Hd) continue;
#pragma unroll
        for (int i = 0; i < 4; i++) {
            int ix = ix0 + i;
            if ((unsigned)ix >= (unsigned)Wd) continue;
            float w = gxv[i] * gyv[j];
            int idx = b * HW + iy * Wd + ix;
            asm volatile("red.global.add.v4.f32 [%0], {%1, %2, %3, %4};"
                         :: "l"(acc + idx), "f"(s0 * w), "f"(s1 * w),
                            "f"(s2 * w),  "f"(f * w)
                         : "memory");
            atomicAdd(accR + idx, w);
        }
    }
}

// ---------------------------------------------------------------------------
// Final adaptive blend
// ---------------------------------------------------------------------------
__global__ void __launch_bounds__(256) k_blend(float* __restrict__ out) {
    int p = blockIdx.x * 256 + threadIdx.x;
    if (p >= BHW) return;
    int b = p / HW;
    int r = p - b * HW;

    float4 A = g_acc4[0][p];  float R1 = g_accR[0][p];
    float4 C = g_acc4[1][p];  float R2 = g_accR[1][p];

    float w1 = A.w / (R1 + THRESH_);
    float w2 = C.w / (R2 + THRESH_);
    float q1 = w1 / (A.w + THRESH_);   // w1 / (pw1 + thresh)
    float q2 = w2 / (C.w + THRESH_);
    float dn = 1.f / (w1 + w2 + EPS_);

    float* ob = out + b * 3 * HW + r;
    ob[0]      = (A.x * q1 + C.x * q2) * dn;
    ob[HW]     = (A.y * q1 + C.y * q2) * dn;
    ob[2 * HW] = (A.z * q1 + C.z * q2) * dn;
}

// ---------------------------------------------------------------------------
extern "C" void kernel_launch(void* const* d_in, const int* in_sizes, int n_in,
                              void* d_out, int out_size)
{
    const float* i1 = (const float*)d_in[0];
    const float* i2 = (const float*)d_in[1];
    const float* f1 = (const float*)d_in[2];
    const float* f2 = (const float*)d_in[3];
    float* out = (float*)d_out;

    constexpr int T = 256;
    int nb = (BHW + T - 1) / T;
    int nz = (2 * BHW + T - 1) / T;

    k_zero<<<nz, T>>>();
    k_err<<<nb, T>>>(i1, i2, f1, 0);
    k_err<<<nb, T>>>(i2, i1, f2, 1);
    k_fw<<<nb, T>>>(0);
    k_fw<<<nb, T>>>(1);
    k_splat<<<nb, T>>>(i1, f1, 0);
    k_splat<<<nb, T>>>(i2, f2, 1);
    k_blend<<<nb, T>>>(out);
}

// round 2
// speedup vs baseline: 1.0026x; 1.0026x over previous
#include <cuda_runtime.h>

// Problem shape (fixed): input1/2 [4,3,720,1280] f32, flow3/4 [4,2,720,1280] f32
namespace {
constexpr int Wd  = 1280;
constexpr int Hd  = 720;
constexpr int Bd  = 4;
constexpr int HW  = Hd * Wd;
constexpr int BHW = Bd * HW;

constexpr float INV_LE  = 255.0f / 30.0f;              // 1 / LAMBDA_E
constexpr float INV2S2  = 1.0f / (2.0f * 1.5f * 1.5f); // 1/(2*sigma_d^2)
constexpr float THRESH_ = 1e-6f;
constexpr float EPS_    = 1e-6f;

constexpr int TX = 32, TY = 8;   // err+fw tile
}

// Scratch: branch-indexed. acc4 = (p_r, p_g, p_b, pw), accR = rw.
__device__ float  g_fw  [2][BHW];
__device__ float4 g_acc4[2][BHW];
__device__ float  g_accR[2][BHW];

// ---------------------------------------------------------------------------
// Zero the splat accumulators (all 16B stores)
// ---------------------------------------------------------------------------
__global__ void __launch_bounds__(256) k_zero() {
    int p = blockIdx.x * 256 + threadIdx.x;
    float4 z = make_float4(0.f, 0.f, 0.f, 0.f);
    if (p < 2 * BHW) (&g_acc4[0][0])[p] = z;
    if (p < 2 * BHW / 4) reinterpret_cast<float4*>(&g_accR[0][0])[p] = z;
}

// ---------------------------------------------------------------------------
// Fused: photometric error (bilinear warp) + 3x3 box + fw = exp(-(e/le)^2)
// One block computes a (TX x TY) tile; err computed on (TX+2)x(TY+2) halo in
// smem (zero outside image, matching SAME zero-padding), then box+exp.
// ---------------------------------------------------------------------------
__device__ __forceinline__ float photo_err(
    const float* __restrict__ i1, const float* __restrict__ i2,
    const float* __restrict__ flow, int b, int x, int y)
{
    int r = y * Wd + x;
    float u = __ldg(flow + b * 2 * HW + r);
    float v = __ldg(flow + b * 2 * HW + HW + r);

    float gx = fminf(fmaxf((float)x + u, 0.f), (float)(Wd - 1));
    float gy = fminf(fmaxf((float)y + v, 0.f), (float)(Hd - 1));
    float x0f = floorf(gx), y0f = floorf(gy);
    int x0 = (int)x0f, y0 = (int)y0f;
    int x1 = min(x0 + 1, Wd - 1), y1 = min(y0 + 1, Hd - 1);
    float wx = gx - x0f, wy = gy - y0f;
    float w00 = (1.f - wx) * (1.f - wy);
    float w01 = wx * (1.f - wy);
    float w10 = (1.f - wx) * wy;
    float w11 = wx * wy;

    const float* i2b = i2 + b * 3 * HW;
    const float* i1b = i1 + b * 3 * HW;
    float e = 0.f;
#pragma unroll
    for (int c = 0; c < 3; c++) {
        const float* ip = i2b + c * HW;
        float wv = __ldg(ip + y0 * Wd + x0) * w00 + __ldg(ip + y0 * Wd + x1) * w01
                 + __ldg(ip + y1 * Wd + x0) * w10 + __ldg(ip + y1 * Wd + x1) * w11;
        e += fabsf(__ldg(i1b + c * HW + r) - wv);
    }
    return e * (1.f / 3.f);
}

__global__ void __launch_bounds__(TX * TY) k_errfw(
    const float* __restrict__ i1, const float* __restrict__ i2,
    const float* __restrict__ flow, int br)
{
    __shared__ float serr[TY + 2][TX + 2];

    int b  = blockIdx.z;
    int bx = blockIdx.x * TX;
    int by = blockIdx.y * TY;
    int t  = threadIdx.y * TX + threadIdx.x;

    // fill (TY+2)x(TX+2) halo-err tile
    for (int idx = t; idx < (TY + 2) * (TX + 2); idx += TX * TY) {
        int j = idx / (TX + 2);
        int i = idx - j * (TX + 2);
        int ex = bx + i - 1;
        int ey = by + j - 1;
        float e = 0.f;
        if ((unsigned)ex < (unsigned)Wd && (unsigned)ey < (unsigned)Hd)
            e = photo_err(i1, i2, flow, b, ex, ey);
        serr[j][i] = e;
    }
    __syncthreads();

    int lx = threadIdx.x, ly = threadIdx.y;
    float s = 0.f;
#pragma unroll
    for (int j = 0; j < 3; j++)
#pragma unroll
        for (int i = 0; i < 3; i++)
            s += serr[ly + j][lx + i];

    float tt = s * (1.f / 9.f) * INV_LE;
    int x = bx + lx, y = by + ly;
    g_fw[br][b * HW + y * Wd + x] = __expf(-tt * tt);
}

// ---------------------------------------------------------------------------
// Forward gaussian splat: 16 taps/pixel; per tap one red.v4 + one red.f32.
// Separable gaussian (8 MUFU exps instead of 16). TAO_R truncation is dead
// for PROW=2, sigma=1.5 (min tap weight exp(-8/4.5)=0.169 > 0.05).
// ---------------------------------------------------------------------------
__global__ void __launch_bounds__(256) k_splat(
    const float* __restrict__ img, const float* __restrict__ flow, int br)
{
    int p = blockIdx.x * 256 + threadIdx.x;
    if (p >= BHW) return;
    int x  = p % Wd;
    int yb = p / Wd;
    int b  = yb / Hd;
    int y  = yb - b * Hd;
    int r  = p - b * HW;

    float u = __ldg(flow + b * 2 * HW + r);
    float v = __ldg(flow + b * 2 * HW + HW + r);
    float f = g_fw[br][p];

    const float* imb = img + b * 3 * HW + r;
    float s0 = __ldg(imb) * f;
    float s1 = __ldg(imb + HW) * f;
    float s2 = __ldg(imb + 2 * HW) * f;

    float tx = (float)x + u, ty = (float)y + v;
    float fx = floorf(tx), fy = floorf(ty);
    int ix0 = (int)fx - 1, iy0 = (int)fy - 1;

    float gxv[4], gyv[4];
#pragma unroll
    for (int k = 0; k < 4; k++) {
        float dx = tx - (fx + (float)(k - 1));
        float dy = ty - (fy + (float)(k - 1));
        gxv[k] = __expf(-dx * dx * INV2S2);
        gyv[k] = __expf(-dy * dy * INV2S2);
    }

    float4* acc  = g_acc4[br];
    float*  accR = g_accR[br];
#pragma unroll
    for (int j = 0; j < 4; j++) {
        int iy = iy0 + j;
        if ((unsigned)iy >= (unsigned)Hd) continue;
        int rowbase = b * HW + iy * Wd;
#pragma unroll
        for (int i = 0; i < 4; i++) {
            int ix = ix0 + i;
            if ((unsigned)ix >= (unsigned)Wd) continue;
            float w = gxv[i] * gyv[j];
            int idx = rowbase + ix;
            asm volatile("red.global.add.v4.f32 [%0], {%1, %2, %3, %4};"
                         :: "l"(acc + idx), "f"(s0 * w), "f"(s1 * w),
                            "f"(s2 * w),  "f"(f * w)
                         : "memory");
            atomicAdd(accR + idx, w);
        }
    }
}

// ---------------------------------------------------------------------------
// Final adaptive blend
// ---------------------------------------------------------------------------
__global__ void __launch_bounds__(256) k_blend(float* __restrict__ out) {
    int p = blockIdx.x * 256 + threadIdx.x;
    if (p >= BHW) return;
    int b = p / HW;
    int r = p - b * HW;

    float4 A = g_acc4[0][p];  float R1 = g_accR[0][p];
    float4 C = g_acc4[1][p];  float R2 = g_accR[1][p];

    float w1 = A.w / (R1 + THRESH_);
    float w2 = C.w / (R2 + THRESH_);
    float q1 = w1 / (A.w + THRESH_);   // w1 / (pw1 + thresh)
    float q2 = w2 / (C.w + THRESH_);
    float dn = 1.f / (w1 + w2 + EPS_);

    float* ob = out + b * 3 * HW + r;
    ob[0]      = (A.x * q1 + C.x * q2) * dn;
    ob[HW]     = (A.y * q1 + C.y * q2) * dn;
    ob[2 * HW] = (A.z * q1 + C.z * q2) * dn;
}

// ---------------------------------------------------------------------------
extern "C" void kernel_launch(void* const* d_in, const int* in_sizes, int n_in,
                              void* d_out, int out_size)
{
    const float* i1 = (const float*)d_in[0];
    const float* i2 = (const float*)d_in[1];
    const float* f1 = (const float*)d_in[2];
    const float* f2 = (const float*)d_in[3];
    float* out = (float*)d_out;

    constexpr int T = 256;
    int nb = (BHW + T - 1) / T;
    int nz = (2 * BHW + T - 1) / T;

    dim3 gfw(Wd / TX, Hd / TY, Bd);
    dim3 bfw(TX, TY, 1);

    k_zero <<<nz, T>>>();              // launch 1
    k_errfw<<<gfw, bfw>>>(i1, i2, f1, 0); // launch 2
    k_errfw<<<gfw, bfw>>>(i2, i1, f2, 1); // launch 3
    k_splat<<<nb, T>>>(i1, f1, 0);     // launch 4
    k_splat<<<nb, T>>>(i2, f2, 1);     // launch 5  <- profiler target
    k_blend<<<nb, T>>>(out);           // launch 6
}

// round 3
// speedup vs baseline: 1.1775x; 1.1745x over previous
#include <cuda_runtime.h>

// Problem shape (fixed): input1/2 [4,3,720,1280] f32, flow3/4 [4,2,720,1280] f32
namespace {
constexpr int Wd  = 1280;
constexpr int Hd  = 720;
constexpr int Bd  = 4;
constexpr int HW  = Hd * Wd;
constexpr int BHW = Bd * HW;

constexpr float INV_LE  = 255.0f / 30.0f;              // 1 / LAMBDA_E
constexpr float INV2S2  = 1.0f / (2.0f * 1.5f * 1.5f); // 1/(2*sigma_d^2)
constexpr float THRESH_ = 1e-6f;
constexpr float EPS_    = 1e-6f;

constexpr int TX = 32, TY = 8;   // err+fw tile
}

// Scratch: branch-indexed. acc4 = (p_r, p_g, p_b, pw), accR = rw (16B-aligned).
__device__ float  g_fw   [2][BHW];
__device__ float4 g_acc4 [2][BHW];
__device__ float4 g_accR4[2][BHW / 4];

// ---------------------------------------------------------------------------
// Fused: photometric error (bilinear warp) + 3x3 box + fw = exp(-(e/le)^2),
// plus zeroing of this tile's splat accumulators (both arrays, this branch).
// ---------------------------------------------------------------------------
__device__ __forceinline__ float photo_err(
    const float* __restrict__ i1, const float* __restrict__ i2,
    const float* __restrict__ flow, int b, int x, int y)
{
    int r = y * Wd + x;
    float u = __ldg(flow + b * 2 * HW + r);
    float v = __ldg(flow + b * 2 * HW + HW + r);

    float gx = fminf(fmaxf((float)x + u, 0.f), (float)(Wd - 1));
    float gy = fminf(fmaxf((float)y + v, 0.f), (float)(Hd - 1));
    float x0f = floorf(gx), y0f = floorf(gy);
    int x0 = (int)x0f, y0 = (int)y0f;
    int x1 = min(x0 + 1, Wd - 1), y1 = min(y0 + 1, Hd - 1);
    float wx = gx - x0f, wy = gy - y0f;
    float w00 = (1.f - wx) * (1.f - wy);
    float w01 = wx * (1.f - wy);
    float w10 = (1.f - wx) * wy;
    float w11 = wx * wy;

    const float* i2b = i2 + b * 3 * HW;
    const float* i1b = i1 + b * 3 * HW;
    float e = 0.f;
#pragma unroll
    for (int c = 0; c < 3; c++) {
        const float* ip = i2b + c * HW;
        float wv = __ldg(ip + y0 * Wd + x0) * w00 + __ldg(ip + y0 * Wd + x1) * w01
                 + __ldg(ip + y1 * Wd + x0) * w10 + __ldg(ip + y1 * Wd + x1) * w11;
        e += fabsf(__ldg(i1b + c * HW + r) - wv);
    }
    return e * (1.f / 3.f);
}

__global__ void __launch_bounds__(TX * TY) k_errfw(
    const float* __restrict__ i1, const float* __restrict__ i2,
    const float* __restrict__ flow, int br)
{
    __shared__ float serr[TY + 2][TX + 2];

    int b  = blockIdx.z;
    int bx = blockIdx.x * TX;
    int by = blockIdx.y * TY;
    int t  = threadIdx.y * TX + threadIdx.x;

    for (int idx = t; idx < (TY + 2) * (TX + 2); idx += TX * TY) {
        int j = idx / (TX + 2);
        int i = idx - j * (TX + 2);
        int ex = bx + i - 1;
        int ey = by + j - 1;
        float e = 0.f;
        if ((unsigned)ex < (unsigned)Wd && (unsigned)ey < (unsigned)Hd)
            e = photo_err(i1, i2, flow, b, ex, ey);
        serr[j][i] = e;
    }
    __syncthreads();

    int lx = threadIdx.x, ly = threadIdx.y;
    float s = 0.f;
#pragma unroll
    for (int j = 0; j < 3; j++)
#pragma unroll
        for (int i = 0; i < 3; i++)
            s += serr[ly + j][lx + i];

    float tt = s * (1.f / 9.f) * INV_LE;
    int x = bx + lx, y = by + ly;
    int pidx = b * HW + y * Wd + x;
    g_fw[br][pidx] = __expf(-tt * tt);

    // zero this pixel's splat accumulators for this branch
    g_acc4[br][pidx] = make_float4(0.f, 0.f, 0.f, 0.f);
    reinterpret_cast<float*>(g_accR4[br])[pidx] = 0.f;
}

// ---------------------------------------------------------------------------
// Forward gaussian splat. Colors+pw: one aligned red.v4 per tap (16).
// rw: per tap-row, 4 consecutive floats covered by <=2 zero-padded aligned
// red.v4 over the containing 8-float window (avg 1.75/row => ~7/pixel).
// OOB x-taps automatically fall outside the window slots. TAO_R truncation is
// dead (min tap weight exp(-8/4.5)=0.169 > 0.05).
// ---------------------------------------------------------------------------
__global__ void __launch_bounds__(256) k_splat(
    const float* __restrict__ img, const float* __restrict__ flow, int br)
{
    int p = blockIdx.x * 256 + threadIdx.x;
    if (p >= BHW) return;
    int x  = p % Wd;
    int yb = p / Wd;
    int b  = yb / Hd;
    int y  = yb - b * Hd;
    int r  = p - b * HW;

    float u = __ldg(flow + b * 2 * HW + r);
    float v = __ldg(flow + b * 2 * HW + HW + r);
    float f = g_fw[br][p];

    const float* imb = img + b * 3 * HW + r;
    float s0 = __ldg(imb) * f;
    float s1 = __ldg(imb + HW) * f;
    float s2 = __ldg(imb + 2 * HW) * f;

    float tx = (float)x + u, ty = (float)y + v;
    float fx = floorf(tx), fy = floorf(ty);
    int ix0 = (int)fx - 1, iy0 = (int)fy - 1;

    // all 16 taps are x-invalid -> nothing to do
    if (ix0 < -3 || ix0 > Wd - 1) return;

    float gxv0, gxv1, gxv2, gxv3, gyv[4];
    {
        float dx0 = tx - (fx - 1.f), dx1 = tx - fx, dx2 = tx - (fx + 1.f), dx3 = tx - (fx + 2.f);
        gxv0 = __expf(-dx0 * dx0 * INV2S2);
        gxv1 = __expf(-dx1 * dx1 * INV2S2);
        gxv2 = __expf(-dx2 * dx2 * INV2S2);
        gxv3 = __expf(-dx3 * dx3 * INV2S2);
#pragma unroll
        for (int k = 0; k < 4; k++) {
            float dy = ty - (fy + (float)(k - 1));
            gyv[k] = __expf(-dy * dy * INV2S2);
        }
    }

    // rw padded-window setup: slots [0,8) at row offset s, tap i -> slot i + d
    int s = min(max(ix0 & ~3, 0), Wd - 8);
    int d = ix0 - s;                    // in [-3, 7]
    float sx[8];
#pragma unroll
    for (int c = 0; c < 8; c++) {
        int i = c - d;
        float t = 0.f;
        t = (i == 0) ? gxv0 : t;
        t = (i == 1) ? gxv1 : t;
        t = (i == 2) ? gxv2 : t;
        t = (i == 3) ? gxv3 : t;
        sx[c] = t;
    }
    bool do0 = (d <= 3);                // first half-window nonzero
    bool do1 = (d >= 1);                // second half-window nonzero

    float4* acc  = g_acc4[br];
    float*  accR = reinterpret_cast<float*>(g_accR4[br]);

#pragma unroll
    for (int j = 0; j < 4; j++) {
        int iy = iy0 + j;
        if ((unsigned)iy >= (unsigned)Hd) continue;
        int rowb = b * HW + iy * Wd;
        float gy = gyv[j];

        // colors + pw : one red.v4 per valid tap
#pragma unroll
        for (int i = 0; i < 4; i++) {
            int ix = ix0 + i;
            if ((unsigned)ix >= (unsigned)Wd) continue;
            float w = ((i == 0) ? gxv0 : (i == 1) ? gxv1 : (i == 2) ? gxv2 : gxv3) * gy;
            asm volatile("red.global.add.v4.f32 [%0], {%1, %2, %3, %4};"
                         :: "l"(acc + rowb + ix), "f"(s0 * w), "f"(s1 * w),
                            "f"(s2 * w), "f"(f * w)
                         : "memory");
        }

        // rw : padded aligned v4s
        float* rp = accR + rowb + s;
        if (do0)
            asm volatile("red.global.add.v4.f32 [%0], {%1, %2, %3, %4};"
                         :: "l"(rp), "f"(sx[0] * gy), "f"(sx[1] * gy),
                            "f"(sx[2] * gy), "f"(sx[3] * gy)
                         : "memory");
        if (do1)
            asm volatile("red.global.add.v4.f32 [%0], {%1, %2, %3, %4};"
                         :: "l"(rp + 4), "f"(sx[4] * gy), "f"(sx[5] * gy),
                            "f"(sx[6] * gy), "f"(sx[7] * gy)
                         : "memory");
    }
}

// ---------------------------------------------------------------------------
// Final adaptive blend
// ---------------------------------------------------------------------------
__global__ void __launch_bounds__(256) k_blend(float* __restrict__ out) {
    int p = blockIdx.x * 256 + threadIdx.x;
    if (p >= BHW) return;
    int b = p / HW;
    int r = p - b * HW;

    float4 A = g_acc4[0][p];  float R1 = reinterpret_cast<const float*>(g_accR4[0])[p];
    float4 C = g_acc4[1][p];  float R2 = reinterpret_cast<const float*>(g_accR4[1])[p];

    float w1 = A.w / (R1 + THRESH_);
    float w2 = C.w / (R2 + THRESH_);
    float q1 = w1 / (A.w + THRESH_);   // w1 / (pw1 + thresh)
    float q2 = w2 / (C.w + THRESH_);
    float dn = 1.f / (w1 + w2 + EPS_);

    float* ob = out + b * 3 * HW + r;
    ob[0]      = (A.x * q1 + C.x * q2) * dn;
    ob[HW]     = (A.y * q1 + C.y * q2) * dn;
    ob[2 * HW] = (A.z * q1 + C.z * q2) * dn;
}

// ---------------------------------------------------------------------------
extern "C" void kernel_launch(void* const* d_in, const int* in_sizes, int n_in,
                              void* d_out, int out_size)
{
    const float* i1 = (const float*)d_in[0];
    const float* i2 = (const float*)d_in[1];
    const float* f1 = (const float*)d_in[2];
    const float* f2 = (const float*)d_in[3];
    float* out = (float*)d_out;

    constexpr int T = 256;
    int nb = (BHW + T - 1) / T;

    dim3 gfw(Wd / TX, Hd / TY, Bd);
    dim3 bfw(TX, TY, 1);

    k_errfw<<<gfw, bfw>>>(i1, i2, f1, 0);  // launch 1 (also zeros branch-0 acc)
    k_errfw<<<gfw, bfw>>>(i2, i1, f2, 1);  // launch 2 (also zeros branch-1 acc)
    k_splat<<<nb, T>>>(i1, f1, 0);         // launch 3
    k_splat<<<nb, T>>>(i2, f2, 1);         // launch 4
    k_blend<<<nb, T>>>(out);               // launch 5  <- profiler lands here; splats profiled at -s shift
}

// round 4
// speedup vs baseline: 1.4482x; 1.2299x over previous
#include <cuda_runtime.h>
#include <cstdint>

// Problem shape (fixed): input1/2 [4,3,720,1280] f32, flow3/4 [4,2,720,1280] f32
namespace {
constexpr int Wd  = 1280;
constexpr int Hd  = 720;
constexpr int Bd  = 4;
constexpr int HW  = Hd * Wd;
constexpr int BHW = Bd * HW;

constexpr float INV_LE  = 255.0f / 30.0f;              // 1 / LAMBDA_E
constexpr float INV2S2  = 1.0f / (2.0f * 1.5f * 1.5f); // 1/(2*sigma_d^2)
constexpr float THRESH_ = 1e-6f;
constexpr float EPS_    = 1e-6f;

constexpr int TX = 32, TY = 8;    // tile for errfw and splat
constexpr int HLO = 8;            // splat smem halo (covers |flow| < 7)
constexpr int SWW = TX + 2 * HLO; // 48
constexpr int SWH = TY + 2 * HLO; // 24
}

// Scratch: branch-indexed. acc4 = (p_r, p_g, p_b, pw), accR = rw.
__device__ float  g_fw   [2][BHW];
__device__ float4 g_acc4 [2][BHW];
__device__ float4 g_accR4[2][BHW / 4];

// ---------------------------------------------------------------------------
// Fused: photometric error (bilinear warp) + 3x3 box + fw = exp(-(e/le)^2),
// plus zeroing of this pixel's splat accumulators. grid.z = b + 4*br.
// ---------------------------------------------------------------------------
__device__ __forceinline__ float photo_err(
    const float* __restrict__ i1, const float* __restrict__ i2,
    const float* __restrict__ flow, int b, int x, int y)
{
    int r = y * Wd + x;
    float u = __ldg(flow + b * 2 * HW + r);
    float v = __ldg(flow + b * 2 * HW + HW + r);

    float gx = fminf(fmaxf((float)x + u, 0.f), (float)(Wd - 1));
    float gy = fminf(fmaxf((float)y + v, 0.f), (float)(Hd - 1));
    float x0f = floorf(gx), y0f = floorf(gy);
    int x0 = (int)x0f, y0 = (int)y0f;
    int x1 = min(x0 + 1, Wd - 1), y1 = min(y0 + 1, Hd - 1);
    float wx = gx - x0f, wy = gy - y0f;
    float w00 = (1.f - wx) * (1.f - wy);
    float w01 = wx * (1.f - wy);
    float w10 = (1.f - wx) * wy;
    float w11 = wx * wy;

    const float* i2b = i2 + b * 3 * HW;
    const float* i1b = i1 + b * 3 * HW;
    float e = 0.f;
#pragma unroll
    for (int c = 0; c < 3; c++) {
        const float* ip = i2b + c * HW;
        float wv = __ldg(ip + y0 * Wd + x0) * w00 + __ldg(ip + y0 * Wd + x1) * w01
                 + __ldg(ip + y1 * Wd + x0) * w10 + __ldg(ip + y1 * Wd + x1) * w11;
        e += fabsf(__ldg(i1b + c * HW + r) - wv);
    }
    return e * (1.f / 3.f);
}

__global__ void __launch_bounds__(TX * TY) k_errfw(
    const float* __restrict__ in1, const float* __restrict__ in2,
    const float* __restrict__ fl1, const float* __restrict__ fl2)
{
    __shared__ float serr[TY + 2][TX + 2];

    int br = blockIdx.z >> 2;
    int b  = blockIdx.z & 3;
    const float* i1   = br ? in2 : in1;
    const float* i2   = br ? in1 : in2;
    const float* flow = br ? fl2 : fl1;

    int bx = blockIdx.x * TX;
    int by = blockIdx.y * TY;
    int t  = threadIdx.y * TX + threadIdx.x;

    for (int idx = t; idx < (TY + 2) * (TX + 2); idx += TX * TY) {
        int j = idx / (TX + 2);
        int i = idx - j * (TX + 2);
        int ex = bx + i - 1;
        int ey = by + j - 1;
        float e = 0.f;
        if ((unsigned)ex < (unsigned)Wd && (unsigned)ey < (unsigned)Hd)
            e = photo_err(i1, i2, flow, b, ex, ey);
        serr[j][i] = e;
    }
    __syncthreads();

    int lx = threadIdx.x, ly = threadIdx.y;
    float s = 0.f;
#pragma unroll
    for (int j = 0; j < 3; j++)
#pragma unroll
        for (int i = 0; i < 3; i++)
            s += serr[ly + j][lx + i];

    float tt = s * (1.f / 9.f) * INV_LE;
    int x = bx + lx, y = by + ly;
    int pidx = b * HW + y * Wd + x;
    g_fw[br][pidx] = __expf(-tt * tt);

    g_acc4[br][pidx] = make_float4(0.f, 0.f, 0.f, 0.f);
    reinterpret_cast<float*>(g_accR4[br])[pidx] = 0.f;
}

// ---------------------------------------------------------------------------
// Forward gaussian splat, hybrid accumulation:
//  - colors+pw: 16 red.v4 per pixel at L2 (irreducible 16B payloads)
//  - rw: shared-memory tile (48x24, halo 8) + cp.reduce.async.bulk row flush;
//    taps outside the window (|flow| >= 7, ~never for N(0,1)) fall back to a
//    direct global atomicAdd for correctness on arbitrary flow.
// TAO_R truncation is dead (min tap weight exp(-8/4.5)=0.169 > 0.05).
// grid.z = b + 4*br.
// ---------------------------------------------------------------------------
__global__ void __launch_bounds__(TX * TY) k_splat(
    const float* __restrict__ in1, const float* __restrict__ in2,
    const float* __restrict__ fl1, const float* __restrict__ fl2)
{
    __shared__ __align__(16) float srw[SWH][SWW];

    int br = blockIdx.z >> 2;
    int b  = blockIdx.z & 3;
    const float* img  = br ? in2 : in1;
    const float* flow = br ? fl2 : fl1;

    int bx = blockIdx.x * TX;
    int by = blockIdx.y * TY;
    int lx = threadIdx.x, ly = threadIdx.y;
    int t  = ly * TX + lx;
    int x  = bx + lx, y = by + ly;
    int r  = y * Wd + x;
    int p  = b * HW + r;

    // zero smem tile
    {
        float4* sz = reinterpret_cast<float4*>(&srw[0][0]);
#pragma unroll
        for (int i = t; i < SWH * SWW / 4; i += TX * TY)
            sz[i] = make_float4(0.f, 0.f, 0.f, 0.f);
    }
    __syncthreads();

    {
        float u = __ldg(flow + b * 2 * HW + r);
        float v = __ldg(flow + b * 2 * HW + HW + r);
        float f = g_fw[br][p];

        const float* imb = img + b * 3 * HW + r;
        float s0 = __ldg(imb) * f;
        float s1 = __ldg(imb + HW) * f;
        float s2 = __ldg(imb + 2 * HW) * f;

        float tx = (float)x + u, ty = (float)y + v;
        float fx = floorf(tx), fy = floorf(ty);
        int ix0 = (int)fx - 1, iy0 = (int)fy - 1;

        float gxv0, gxv1, gxv2, gxv3, gyv[4];
        {
            float dx0 = tx - (fx - 1.f), dx1 = tx - fx;
            float dx2 = tx - (fx + 1.f), dx3 = tx - (fx + 2.f);
            gxv0 = __expf(-dx0 * dx0 * INV2S2);
            gxv1 = __expf(-dx1 * dx1 * INV2S2);
            gxv2 = __expf(-dx2 * dx2 * INV2S2);
            gxv3 = __expf(-dx3 * dx3 * INV2S2);
#pragma unroll
            for (int k = 0; k < 4; k++) {
                float dy = ty - (fy + (float)(k - 1));
                gyv[k] = __expf(-dy * dy * INV2S2);
            }
        }

        float4* acc  = g_acc4[br];
        float*  accR = reinterpret_cast<float*>(g_accR4[br]);
        int xw0 = bx - HLO, yw0 = by - HLO;

#pragma unroll
        for (int j = 0; j < 4; j++) {
            int iy = iy0 + j;
            if ((unsigned)iy >= (unsigned)Hd) continue;
            int rowb = b * HW + iy * Wd;
            float gy = gyv[j];
            int sy = iy - yw0;
#pragma unroll
            for (int i = 0; i < 4; i++) {
                int ix = ix0 + i;
                if ((unsigned)ix >= (unsigned)Wd) continue;
                float w = ((i == 0) ? gxv0 : (i == 1) ? gxv1 : (i == 2) ? gxv2 : gxv3) * gy;
                asm volatile("red.global.add.v4.f32 [%0], {%1, %2, %3, %4};"
                             :: "l"(acc + rowb + ix), "f"(s0 * w), "f"(s1 * w),
                                "f"(s2 * w), "f"(f * w)
                             : "memory");
                int sx = ix - xw0;
                if ((unsigned)sx < (unsigned)SWW && (unsigned)sy < (unsigned)SWH)
                    atomicAdd(&srw[sy][sx], w);
                else
                    atomicAdd(accR + rowb + ix, w);   // ~never taken for N(0,1) flow
            }
        }
    }
    __syncthreads();

    // flush rw tile: one bulk async reduce per valid row (threads 0..SWH-1)
    if (t < SWH) {
        int yy = by - HLO + t;
        if ((unsigned)yy < (unsigned)Hd) {
            int xs = max(bx - HLO, 0);
            int xe = min(bx + TX + HLO, Wd);
            int nbytes = (xe - xs) * 4;                 // multiple of 16 (bounds are mult. of 8)
            float* dst = reinterpret_cast<float*>(g_accR4[br]) + b * HW + yy * Wd + xs;
            uint32_t saddr = (uint32_t)__cvta_generic_to_shared(&srw[t][xs - (bx - HLO)]);
            asm volatile("fence.proxy.async.shared::cta;" ::: "memory");
            asm volatile("cp.reduce.async.bulk.global.shared::cta.bulk_group.add.f32 "
                         "[%0], [%1], %2;"
                         :: "l"(dst), "r"(saddr), "r"(nbytes) : "memory");
            asm volatile("cp.async.bulk.commit_group;" ::: "memory");
            asm volatile("cp.async.bulk.wait_group 0;" ::: "memory");
        }
    }
}

// ---------------------------------------------------------------------------
// Final adaptive blend
// ---------------------------------------------------------------------------
__global__ void __launch_bounds__(256) k_blend(float* __restrict__ out) {
    int p = blockIdx.x * 256 + threadIdx.x;
    if (p >= BHW) return;
    int b = p / HW;
    int r = p - b * HW;

    float4 A = g_acc4[0][p];  float R1 = reinterpret_cast<const float*>(g_accR4[0])[p];
    float4 C = g_acc4[1][p];  float R2 = reinterpret_cast<const float*>(g_accR4[1])[p];

    float w1 = A.w / (R1 + THRESH_);
    float w2 = C.w / (R2 + THRESH_);
    float q1 = w1 / (A.w + THRESH_);   // w1 / (pw1 + thresh)
    float q2 = w2 / (C.w + THRESH_);
    float dn = 1.f / (w1 + w2 + EPS_);

    float* ob = out + b * 3 * HW + r;
    ob[0]      = (A.x * q1 + C.x * q2) * dn;
    ob[HW]     = (A.y * q1 + C.y * q2) * dn;
    ob[2 * HW] = (A.z * q1 + C.z * q2) * dn;
}

// ---------------------------------------------------------------------------
extern "C" void kernel_launch(void* const* d_in, const int* in_sizes, int n_in,
                              void* d_out, int out_size)
{
    const float* i1 = (const float*)d_in[0];
    const float* i2 = (const float*)d_in[1];
    const float* f1 = (const float*)d_in[2];
    const float* f2 = (const float*)d_in[3];
    float* out = (float*)d_out;

    dim3 g(Wd / TX, Hd / TY, Bd * 2);
    dim3 blk(TX, TY, 1);
    int nb = (BHW + 255) / 256;

    k_errfw<<<g, blk>>>(i1, i2, f1, f2);   // both branches; also zeros accumulators
    k_splat<<<g, blk>>>(i1, i2, f1, f2);   // both branches
    k_blend<<<nb, 256>>>(out);
}